// round 3
// baseline (speedup 1.0000x reference)
#include <cuda_runtime.h>
#include <cuda_bf16.h>
#include <cstdint>

#define N_NODES 100000
#define N_EDGES 1600000
#define FDIM    128
#define N_GRAPHS 2048
#define NB_SCAN ((N_NODES + 1023) / 1024)   // 98

// ---------------- scratch (static device globals; no allocation) ----------------
__device__ int   g_is64;                  // 1 if index buffers are int64
__device__ int   g_deg[N_NODES];          // edge-count per target (excl. self loop)
__device__ float g_dis[N_NODES];          // d^{-1/2} including self loop
__device__ int   g_ptr[N_NODES + 1];      // CSR row pointers (by target)
__device__ int   g_cur[N_NODES];          // fill cursors
__device__ int   g_src[N_EDGES];          // CSR: source node per edge
__device__ float g_nrm[N_EDGES];          // CSR: norm per edge
__device__ int   g_bsum[NB_SCAN];         // scan block sums
__device__ float g_h[(size_t)N_NODES * FDIM];  // GEMM output
__device__ float g_a[(size_t)N_NODES * FDIM];  // layer output
__device__ float g_cnt[N_GRAPHS];

// index load that works for both int32 and int64 buffers
__device__ __forceinline__ int load_idx(const void* buf, long long i, int is64) {
    if (is64) return (int)((const long long*)buf)[i];
    return ((const int*)buf)[i];
}

// ---------------- dtype detection ----------------
// int64 little-endian values < 2^31  => every odd 32-bit word is 0.
// int32 random indices in [0,100000) => 256 odd words all-zero has prob ~0.
__global__ void k_detect(const int* __restrict__ ei_raw) {
    if (threadIdx.x == 0 && blockIdx.x == 0) {
        int ornz = 0;
        for (int i = 0; i < 256; i++) ornz |= ei_raw[2 * i + 1];
        g_is64 = (ornz == 0) ? 1 : 0;
    }
}

// ---------------- preprocessing ----------------
__global__ void k_zero_deg() {
    int i = blockIdx.x * blockDim.x + threadIdx.x;
    if (i < N_NODES) g_deg[i] = 0;
}

__global__ void k_count(const void* __restrict__ ei) {
    int e = blockIdx.x * blockDim.x + threadIdx.x;
    int is64 = g_is64;
    if (e < N_EDGES) {
        int c = load_idx(ei, (long long)N_EDGES + e, is64);
        atomicAdd(&g_deg[c], 1);
    }
}

__global__ void k_dis() {
    int i = blockIdx.x * blockDim.x + threadIdx.x;
    if (i < N_NODES) g_dis[i] = rsqrtf((float)(g_deg[i] + 1));
}

__global__ void k_scan1() {
    __shared__ int s[1024];
    int i = blockIdx.x * 1024 + threadIdx.x;
    int v = (i < N_NODES) ? g_deg[i] : 0;
    s[threadIdx.x] = v;
    __syncthreads();
#pragma unroll
    for (int off = 1; off < 1024; off <<= 1) {
        int t = 0;
        if ((int)threadIdx.x >= off) t = s[threadIdx.x - off];
        __syncthreads();
        s[threadIdx.x] += t;
        __syncthreads();
    }
    if (i < N_NODES) g_ptr[i] = s[threadIdx.x] - v;   // exclusive within chunk
    if (threadIdx.x == 1023) g_bsum[blockIdx.x] = s[1023];
}

__global__ void k_scan2() {   // single block, 128 threads; NB_SCAN <= 128
    __shared__ int s[128];
    int v = ((int)threadIdx.x < NB_SCAN) ? g_bsum[threadIdx.x] : 0;
    s[threadIdx.x] = v;
    __syncthreads();
#pragma unroll
    for (int off = 1; off < 128; off <<= 1) {
        int t = 0;
        if ((int)threadIdx.x >= off) t = s[threadIdx.x - off];
        __syncthreads();
        s[threadIdx.x] += t;
        __syncthreads();
    }
    if ((int)threadIdx.x < NB_SCAN) g_bsum[threadIdx.x] = s[threadIdx.x] - v;
}

__global__ void k_scan3() {
    int i = blockIdx.x * 1024 + threadIdx.x;
    if (i < N_NODES) {
        g_ptr[i] += g_bsum[blockIdx.x];
        g_cur[i] = g_ptr[i];
    }
    if (i == 0) g_ptr[N_NODES] = N_EDGES;
}

__global__ void k_fill(const void* __restrict__ ei) {
    int e = blockIdx.x * blockDim.x + threadIdx.x;
    int is64 = g_is64;
    if (e < N_EDGES) {
        int r = load_idx(ei, e, is64);
        int c = load_idx(ei, (long long)N_EDGES + e, is64);
        int pos = atomicAdd(&g_cur[c], 1);
        g_src[pos] = r;
        g_nrm[pos] = g_dis[r] * g_dis[c];
    }
}

// ---------------- SGEMM: C[n,128] = A[n,128] @ W[128,128] ----------------
// 128x128 block tile, BK=16, 256 threads, 8x8 microtile per thread.
__global__ void k_gemm(const float* __restrict__ A, const float* __restrict__ W,
                       float* __restrict__ C, int n) {
    __shared__ float sA[16][128];   // [k][m] (transposed)
    __shared__ float sW[16][128];   // [k][n]
    const int tid = threadIdx.x;
    const int block_row = blockIdx.x * 128;
    const int trow = (tid / 16) * 8;
    const int tcol = (tid % 16) * 8;
    float acc[8][8] = {};

    for (int k0 = 0; k0 < 128; k0 += 16) {
#pragma unroll
        for (int i = 0; i < 2; i++) {
            int f  = tid * 2 + i;          // 0..511
            int r  = f >> 2;               // row in tile
            int kq = (f & 3) << 2;         // k offset (0,4,8,12)
            int grow = block_row + r;
            float4 v = make_float4(0.f, 0.f, 0.f, 0.f);
            if (grow < n)
                v = *(const float4*)(A + (size_t)grow * FDIM + k0 + kq);
            sA[kq + 0][r] = v.x;
            sA[kq + 1][r] = v.y;
            sA[kq + 2][r] = v.z;
            sA[kq + 3][r] = v.w;
        }
#pragma unroll
        for (int i = 0; i < 2; i++) {
            int f  = tid * 2 + i;
            int kk = f >> 5;               // 0..15
            int c  = (f & 31) << 2;        // 0..124
            *(float4*)&sW[kk][c] = *(const float4*)(W + (size_t)(k0 + kk) * FDIM + c);
        }
        __syncthreads();
#pragma unroll
        for (int kk = 0; kk < 16; kk++) {
            float a[8], b[8];
            *(float4*)&a[0] = *(float4*)&sA[kk][trow];
            *(float4*)&a[4] = *(float4*)&sA[kk][trow + 4];
            *(float4*)&b[0] = *(float4*)&sW[kk][tcol];
            *(float4*)&b[4] = *(float4*)&sW[kk][tcol + 4];
#pragma unroll
            for (int i = 0; i < 8; i++)
#pragma unroll
                for (int j = 0; j < 8; j++)
                    acc[i][j] += a[i] * b[j];
        }
        __syncthreads();
    }
#pragma unroll
    for (int i = 0; i < 8; i++) {
        int grow = block_row + trow + i;
        if (grow < n) {
            float* crow = C + (size_t)grow * FDIM + tcol;
            *(float4*)(crow)     = make_float4(acc[i][0], acc[i][1], acc[i][2], acc[i][3]);
            *(float4*)(crow + 4) = make_float4(acc[i][4], acc[i][5], acc[i][6], acc[i][7]);
        }
    }
}

// ---------------- aggregation: out[v] = relu(sum_e nrm*h[src] + selfnorm*h[v] + b) ----------------
// one warp per node, float4 per lane (128 features)
__global__ void k_agg(const float* __restrict__ h, const float* __restrict__ bias,
                      float* __restrict__ out) {
    int node = (blockIdx.x * blockDim.x + threadIdx.x) >> 5;
    if (node >= N_NODES) return;
    int lane = threadIdx.x & 31;

    int beg = g_ptr[node];
    int end = g_ptr[node + 1];
    float sn = 1.0f / (float)(g_deg[node] + 1);   // dis^2 self-loop norm

    float4 v = ((const float4*)(h + (size_t)node * FDIM))[lane];
    float4 acc = make_float4(sn * v.x, sn * v.y, sn * v.z, sn * v.w);

    for (int e = beg; e < end; e++) {
        int   r = g_src[e];
        float w = g_nrm[e];
        float4 u = ((const float4*)(h + (size_t)r * FDIM))[lane];
        acc.x += w * u.x;
        acc.y += w * u.y;
        acc.z += w * u.z;
        acc.w += w * u.w;
    }
    float4 bb = ((const float4*)bias)[lane];
    acc.x = fmaxf(acc.x + bb.x, 0.0f);
    acc.y = fmaxf(acc.y + bb.y, 0.0f);
    acc.z = fmaxf(acc.z + bb.z, 0.0f);
    acc.w = fmaxf(acc.w + bb.w, 0.0f);
    ((float4*)(out + (size_t)node * FDIM))[lane] = acc;
}

// ---------------- pooling ----------------
__global__ void k_pool_zero(float* __restrict__ out) {
    int i = blockIdx.x * blockDim.x + threadIdx.x;
    if (i < N_GRAPHS * FDIM) out[i] = 0.0f;
    if (i < N_GRAPHS) g_cnt[i] = 0.0f;
}

__global__ void k_pool(const float* __restrict__ a, const void* __restrict__ batch,
                       float* __restrict__ out) {
    int node = (blockIdx.x * blockDim.x + threadIdx.x) >> 5;
    if (node >= N_NODES) return;
    int lane = threadIdx.x & 31;
    int g = load_idx(batch, node, g_is64);
    float4 v = ((const float4*)(a + (size_t)node * FDIM))[lane];
    float* dst = out + (size_t)g * FDIM + lane * 4;
    atomicAdd(dst + 0, v.x);
    atomicAdd(dst + 1, v.y);
    atomicAdd(dst + 2, v.z);
    atomicAdd(dst + 3, v.w);
    if (lane == 0) atomicAdd(&g_cnt[g], 1.0f);
}

__global__ void k_pool_div(float* __restrict__ out) {
    int i = blockIdx.x * blockDim.x + threadIdx.x;
    if (i < N_GRAPHS * FDIM) out[i] /= fmaxf(g_cnt[i >> 7], 1.0f);
}

// ---------------- launch ----------------
extern "C" void kernel_launch(void* const* d_in, const int* in_sizes, int n_in,
                              void* d_out, int out_size) {
    // Bind inputs by element count (robust to ordering AND to int32/int64 width,
    // since in_sizes is an element count either way):
    //   12800000 -> x ; 16384 -> W1..W4 ; 128 -> b1..b4 ;
    //   3200000  -> edge_index ; 100000 -> batch
    const float* x = nullptr;
    const float* W[4] = {nullptr, nullptr, nullptr, nullptr};
    const float* b[4] = {nullptr, nullptr, nullptr, nullptr};
    const void* ei = nullptr;
    const void* batch = nullptr;
    int nw = 0, nb = 0;
    for (int i = 0; i < n_in; i++) {
        switch (in_sizes[i]) {
            case N_NODES * FDIM:      x = (const float*)d_in[i]; break;
            case FDIM * FDIM:         if (nw < 4) W[nw++] = (const float*)d_in[i]; break;
            case FDIM:                if (nb < 4) b[nb++] = (const float*)d_in[i]; break;
            case 2 * N_EDGES:         ei = d_in[i]; break;
            case N_NODES:             batch = d_in[i]; break;
            default: break;
        }
    }
    // positional fallback (reference arg order) if size-matching failed
    if (!x && n_in >= 11) {
        x = (const float*)d_in[0];
        W[0] = (const float*)d_in[1]; b[0] = (const float*)d_in[2];
        W[1] = (const float*)d_in[3]; b[1] = (const float*)d_in[4];
        W[2] = (const float*)d_in[5]; b[2] = (const float*)d_in[6];
        W[3] = (const float*)d_in[7]; b[3] = (const float*)d_in[8];
        ei = d_in[9]; batch = d_in[10];
    }
    float* out = (float*)d_out;

    float* gh; cudaGetSymbolAddress((void**)&gh, g_h);
    float* ga; cudaGetSymbolAddress((void**)&ga, g_a);

    const int TPB = 256;
    // dtype detection + preprocessing
    k_detect<<<1, 32>>>((const int*)ei);
    k_zero_deg<<<(N_NODES + TPB - 1) / TPB, TPB>>>();
    k_count<<<(N_EDGES + TPB - 1) / TPB, TPB>>>(ei);
    k_dis<<<(N_NODES + TPB - 1) / TPB, TPB>>>();
    k_scan1<<<NB_SCAN, 1024>>>();
    k_scan2<<<1, 128>>>();
    k_scan3<<<NB_SCAN, 1024>>>();
    k_fill<<<(N_EDGES + TPB - 1) / TPB, TPB>>>(ei);

    const int gemm_blocks = (N_NODES + 127) / 128;
    const int agg_blocks  = (N_NODES * 32 + TPB - 1) / TPB;

    // 4 GCN layers
    k_gemm<<<gemm_blocks, 256>>>(x,  W[0], gh, N_NODES);
    k_agg<<<agg_blocks, TPB>>>(gh, b[0], ga);
    k_gemm<<<gemm_blocks, 256>>>(ga, W[1], gh, N_NODES);
    k_agg<<<agg_blocks, TPB>>>(gh, b[1], ga);
    k_gemm<<<gemm_blocks, 256>>>(ga, W[2], gh, N_NODES);
    k_agg<<<agg_blocks, TPB>>>(gh, b[2], ga);
    k_gemm<<<gemm_blocks, 256>>>(ga, W[3], gh, N_NODES);
    k_agg<<<agg_blocks, TPB>>>(gh, b[3], ga);

    // pooling
    k_pool_zero<<<(N_GRAPHS * FDIM + TPB - 1) / TPB, TPB>>>(out);
    k_pool<<<agg_blocks, TPB>>>(ga, batch, out);
    k_pool_div<<<(N_GRAPHS * FDIM + TPB - 1) / TPB, TPB>>>(out);
}

// round 4
// speedup vs baseline: 1.0125x; 1.0125x over previous
#include <cuda_runtime.h>
#include <cuda_bf16.h>
#include <cstdint>

#define N_NODES 100000
#define N_EDGES 1600000
#define FDIM    128
#define N_GRAPHS 2048
#define NB_SCAN ((N_NODES + 1023) / 1024)   // 98

// ---------------- scratch (static device globals; no allocation) ----------------
__device__ int   g_is64;                  // 1 if index buffers are int64
__device__ int   g_deg[N_NODES];          // edge-count per target (excl. self loop)
__device__ float g_dis[N_NODES];          // d^{-1/2} including self loop
__device__ int   g_ptr[N_NODES + 1];      // CSR row pointers (by target)
__device__ int   g_cur[N_NODES];          // fill cursors
__device__ int   g_src[N_EDGES];          // CSR: source node per edge
__device__ float g_nrm[N_EDGES];          // CSR: norm per edge
__device__ int   g_bsum[NB_SCAN];         // scan block sums
__device__ float g_h[(size_t)N_NODES * FDIM];  // GEMM output
__device__ float g_a[(size_t)N_NODES * FDIM];  // layer output
__device__ float g_cnt[N_GRAPHS];

// index load that works for both int32 and int64 buffers
__device__ __forceinline__ int load_idx(const void* buf, long long i, int is64) {
    if (is64) return (int)((const long long*)buf)[i];
    return ((const int*)buf)[i];
}

// packed fp32x2 helpers (Blackwell full-rate FFMA path; ptxas won't auto-fuse)
__device__ __forceinline__ unsigned long long pack_dup_f32(float v) {
    unsigned long long r;
    asm("mov.b64 %0, {%1, %1};" : "=l"(r) : "f"(v));
    return r;
}
__device__ __forceinline__ void ffma2(unsigned long long& acc, unsigned long long a,
                                      unsigned long long b) {
    asm("fma.rn.f32x2 %0, %1, %2, %0;" : "+l"(acc) : "l"(a), "l"(b));
}

// ---------------- dtype detection ----------------
// int64 little-endian values < 2^31  => every odd 32-bit word is 0.
// int32 random indices in [0,100000) => 256 odd words all-zero has prob ~0.
__global__ void k_detect(const int* __restrict__ ei_raw) {
    if (threadIdx.x == 0 && blockIdx.x == 0) {
        int ornz = 0;
        for (int i = 0; i < 256; i++) ornz |= ei_raw[2 * i + 1];
        g_is64 = (ornz == 0) ? 1 : 0;
    }
}

// ---------------- preprocessing ----------------
__global__ void k_zero_deg() {
    int i = blockIdx.x * blockDim.x + threadIdx.x;
    if (i < N_NODES) g_deg[i] = 0;
}

__global__ void k_count(const void* __restrict__ ei) {
    int e = blockIdx.x * blockDim.x + threadIdx.x;
    int is64 = g_is64;
    if (e < N_EDGES) {
        int c = load_idx(ei, (long long)N_EDGES + e, is64);
        atomicAdd(&g_deg[c], 1);
    }
}

__global__ void k_dis() {
    int i = blockIdx.x * blockDim.x + threadIdx.x;
    if (i < N_NODES) g_dis[i] = rsqrtf((float)(g_deg[i] + 1));
}

__global__ void k_scan1() {
    __shared__ int s[1024];
    int i = blockIdx.x * 1024 + threadIdx.x;
    int v = (i < N_NODES) ? g_deg[i] : 0;
    s[threadIdx.x] = v;
    __syncthreads();
#pragma unroll
    for (int off = 1; off < 1024; off <<= 1) {
        int t = 0;
        if ((int)threadIdx.x >= off) t = s[threadIdx.x - off];
        __syncthreads();
        s[threadIdx.x] += t;
        __syncthreads();
    }
    if (i < N_NODES) g_ptr[i] = s[threadIdx.x] - v;   // exclusive within chunk
    if (threadIdx.x == 1023) g_bsum[blockIdx.x] = s[1023];
}

__global__ void k_scan2() {   // single block, 128 threads; NB_SCAN <= 128
    __shared__ int s[128];
    int v = ((int)threadIdx.x < NB_SCAN) ? g_bsum[threadIdx.x] : 0;
    s[threadIdx.x] = v;
    __syncthreads();
#pragma unroll
    for (int off = 1; off < 128; off <<= 1) {
        int t = 0;
        if ((int)threadIdx.x >= off) t = s[threadIdx.x - off];
        __syncthreads();
        s[threadIdx.x] += t;
        __syncthreads();
    }
    if ((int)threadIdx.x < NB_SCAN) g_bsum[threadIdx.x] = s[threadIdx.x] - v;
}

__global__ void k_scan3() {
    int i = blockIdx.x * 1024 + threadIdx.x;
    if (i < N_NODES) {
        g_ptr[i] += g_bsum[blockIdx.x];
        g_cur[i] = g_ptr[i];
    }
    if (i == 0) g_ptr[N_NODES] = N_EDGES;
}

__global__ void k_fill(const void* __restrict__ ei) {
    int e = blockIdx.x * blockDim.x + threadIdx.x;
    int is64 = g_is64;
    if (e < N_EDGES) {
        int r = load_idx(ei, e, is64);
        int c = load_idx(ei, (long long)N_EDGES + e, is64);
        int pos = atomicAdd(&g_cur[c], 1);
        g_src[pos] = r;
        g_nrm[pos] = g_dis[r] * g_dis[c];
    }
}

// ---------------- SGEMM: C[n,128] = A[n,128] @ W[128,128] ----------------
// 128x128 block tile, BK=16, 256 threads, 8x8 microtile per thread.
// Inner product in packed fp32x2 (FFMA2): acc pairs over adjacent output cols.
__global__ void __launch_bounds__(256) k_gemm(const float* __restrict__ A,
                                              const float* __restrict__ W,
                                              float* __restrict__ C, int n) {
    __shared__ float sA[16][128];   // [k][m] (transposed)
    __shared__ float sW[16][128];   // [k][n]
    const int tid = threadIdx.x;
    const int block_row = blockIdx.x * 128;
    const int trow = (tid / 16) * 8;
    const int tcol = (tid % 16) * 8;
    unsigned long long acc2[8][4];  // acc2[i][jp] = (C[i][2jp], C[i][2jp+1]) packed
#pragma unroll
    for (int i = 0; i < 8; i++)
#pragma unroll
        for (int j = 0; j < 4; j++) acc2[i][j] = 0ull;

    for (int k0 = 0; k0 < 128; k0 += 16) {
#pragma unroll
        for (int i = 0; i < 2; i++) {
            int f  = tid * 2 + i;          // 0..511
            int r  = f >> 2;               // row in tile
            int kq = (f & 3) << 2;         // k offset (0,4,8,12)
            int grow = block_row + r;
            float4 v = make_float4(0.f, 0.f, 0.f, 0.f);
            if (grow < n)
                v = *(const float4*)(A + (size_t)grow * FDIM + k0 + kq);
            sA[kq + 0][r] = v.x;
            sA[kq + 1][r] = v.y;
            sA[kq + 2][r] = v.z;
            sA[kq + 3][r] = v.w;
        }
#pragma unroll
        for (int i = 0; i < 2; i++) {
            int f  = tid * 2 + i;
            int kk = f >> 5;               // 0..15
            int c  = (f & 31) << 2;        // 0..124
            *(float4*)&sW[kk][c] = *(const float4*)(W + (size_t)(k0 + kk) * FDIM + c);
        }
        __syncthreads();
#pragma unroll
        for (int kk = 0; kk < 16; kk++) {
            float a[8];
            float4 b0, b1;
            *(float4*)&a[0] = *(float4*)&sA[kk][trow];
            *(float4*)&a[4] = *(float4*)&sA[kk][trow + 4];
            b0 = *(float4*)&sW[kk][tcol];
            b1 = *(float4*)&sW[kk][tcol + 4];
            unsigned long long bp[4];
            bp[0] = *(unsigned long long*)&b0.x;   // (b[0], b[1])
            bp[1] = *(unsigned long long*)&b0.z;   // (b[2], b[3])
            bp[2] = *(unsigned long long*)&b1.x;   // (b[4], b[5])
            bp[3] = *(unsigned long long*)&b1.z;   // (b[6], b[7])
#pragma unroll
            for (int i = 0; i < 8; i++) {
                unsigned long long ad = pack_dup_f32(a[i]);
                ffma2(acc2[i][0], ad, bp[0]);
                ffma2(acc2[i][1], ad, bp[1]);
                ffma2(acc2[i][2], ad, bp[2]);
                ffma2(acc2[i][3], ad, bp[3]);
            }
        }
        __syncthreads();
    }
#pragma unroll
    for (int i = 0; i < 8; i++) {
        int grow = block_row + trow + i;
        if (grow < n) {
            const float* r8 = (const float*)&acc2[i][0];   // 8 contiguous col values
            float* crow = C + (size_t)grow * FDIM + tcol;
            *(float4*)(crow)     = make_float4(r8[0], r8[1], r8[2], r8[3]);
            *(float4*)(crow + 4) = make_float4(r8[4], r8[5], r8[6], r8[7]);
        }
    }
}

// ---------------- aggregation: out[v] = relu(sum_e nrm*h[src] + selfnorm*h[v] + b) ----------------
// one warp per node, float4 per lane (128 features), edge loop unrolled x4 for MLP
__global__ void k_agg(const float* __restrict__ h, const float* __restrict__ bias,
                      float* __restrict__ out) {
    int node = (blockIdx.x * blockDim.x + threadIdx.x) >> 5;
    if (node >= N_NODES) return;
    int lane = threadIdx.x & 31;

    int beg = g_ptr[node];
    int end = g_ptr[node + 1];
    float sn = 1.0f / (float)(g_deg[node] + 1);   // dis^2 self-loop norm

    float4 v = ((const float4*)(h + (size_t)node * FDIM))[lane];
    float4 acc = make_float4(sn * v.x, sn * v.y, sn * v.z, sn * v.w);

    int e = beg;
    for (; e + 4 <= end; e += 4) {
        int   r0 = g_src[e],     r1 = g_src[e + 1];
        int   r2 = g_src[e + 2], r3 = g_src[e + 3];
        float w0 = g_nrm[e],     w1 = g_nrm[e + 1];
        float w2 = g_nrm[e + 2], w3 = g_nrm[e + 3];
        float4 u0 = ((const float4*)(h + (size_t)r0 * FDIM))[lane];
        float4 u1 = ((const float4*)(h + (size_t)r1 * FDIM))[lane];
        float4 u2 = ((const float4*)(h + (size_t)r2 * FDIM))[lane];
        float4 u3 = ((const float4*)(h + (size_t)r3 * FDIM))[lane];
        acc.x += w0 * u0.x + w1 * u1.x + w2 * u2.x + w3 * u3.x;
        acc.y += w0 * u0.y + w1 * u1.y + w2 * u2.y + w3 * u3.y;
        acc.z += w0 * u0.z + w1 * u1.z + w2 * u2.z + w3 * u3.z;
        acc.w += w0 * u0.w + w1 * u1.w + w2 * u2.w + w3 * u3.w;
    }
    for (; e < end; e++) {
        int   r = g_src[e];
        float w = g_nrm[e];
        float4 u = ((const float4*)(h + (size_t)r * FDIM))[lane];
        acc.x += w * u.x;
        acc.y += w * u.y;
        acc.z += w * u.z;
        acc.w += w * u.w;
    }
    float4 bb = ((const float4*)bias)[lane];
    acc.x = fmaxf(acc.x + bb.x, 0.0f);
    acc.y = fmaxf(acc.y + bb.y, 0.0f);
    acc.z = fmaxf(acc.z + bb.z, 0.0f);
    acc.w = fmaxf(acc.w + bb.w, 0.0f);
    ((float4*)(out + (size_t)node * FDIM))[lane] = acc;
}

// ---------------- pooling ----------------
__global__ void k_pool_zero(float* __restrict__ out) {
    int i = blockIdx.x * blockDim.x + threadIdx.x;
    if (i < N_GRAPHS * FDIM) out[i] = 0.0f;
    if (i < N_GRAPHS) g_cnt[i] = 0.0f;
}

__global__ void k_pool(const float* __restrict__ a, const void* __restrict__ batch,
                       float* __restrict__ out) {
    int node = (blockIdx.x * blockDim.x + threadIdx.x) >> 5;
    if (node >= N_NODES) return;
    int lane = threadIdx.x & 31;
    int g = load_idx(batch, node, g_is64);
    float4 v = ((const float4*)(a + (size_t)node * FDIM))[lane];
    float* dst = out + (size_t)g * FDIM + lane * 4;
    atomicAdd(dst + 0, v.x);
    atomicAdd(dst + 1, v.y);
    atomicAdd(dst + 2, v.z);
    atomicAdd(dst + 3, v.w);
    if (lane == 0) atomicAdd(&g_cnt[g], 1.0f);
}

__global__ void k_pool_div(float* __restrict__ out) {
    int i = blockIdx.x * blockDim.x + threadIdx.x;
    if (i < N_GRAPHS * FDIM) out[i] /= fmaxf(g_cnt[i >> 7], 1.0f);
}

// ---------------- launch ----------------
extern "C" void kernel_launch(void* const* d_in, const int* in_sizes, int n_in,
                              void* d_out, int out_size) {
    // Bind inputs by element count (robust to ordering and index width):
    //   12800000 -> x ; 16384 -> W1..W4 ; 128 -> b1..b4 ;
    //   3200000  -> edge_index ; 100000 -> batch
    const float* x = nullptr;
    const float* W[4] = {nullptr, nullptr, nullptr, nullptr};
    const float* b[4] = {nullptr, nullptr, nullptr, nullptr};
    const void* ei = nullptr;
    const void* batch = nullptr;
    int nw = 0, nb = 0;
    for (int i = 0; i < n_in; i++) {
        switch (in_sizes[i]) {
            case N_NODES * FDIM:      x = (const float*)d_in[i]; break;
            case FDIM * FDIM:         if (nw < 4) W[nw++] = (const float*)d_in[i]; break;
            case FDIM:                if (nb < 4) b[nb++] = (const float*)d_in[i]; break;
            case 2 * N_EDGES:         ei = d_in[i]; break;
            case N_NODES:             batch = d_in[i]; break;
            default: break;
        }
    }
    if (!x && n_in >= 11) {   // positional fallback
        x = (const float*)d_in[0];
        W[0] = (const float*)d_in[1]; b[0] = (const float*)d_in[2];
        W[1] = (const float*)d_in[3]; b[1] = (const float*)d_in[4];
        W[2] = (const float*)d_in[5]; b[2] = (const float*)d_in[6];
        W[3] = (const float*)d_in[7]; b[3] = (const float*)d_in[8];
        ei = d_in[9]; batch = d_in[10];
    }
    float* out = (float*)d_out;

    float* gh; cudaGetSymbolAddress((void**)&gh, g_h);
    float* ga; cudaGetSymbolAddress((void**)&ga, g_a);

    const int TPB = 256;
    // dtype detection + preprocessing
    k_detect<<<1, 32>>>((const int*)ei);
    k_zero_deg<<<(N_NODES + TPB - 1) / TPB, TPB>>>();
    k_count<<<(N_EDGES + TPB - 1) / TPB, TPB>>>(ei);
    k_dis<<<(N_NODES + TPB - 1) / TPB, TPB>>>();
    k_scan1<<<NB_SCAN, 1024>>>();
    k_scan2<<<1, 128>>>();
    k_scan3<<<NB_SCAN, 1024>>>();
    k_fill<<<(N_EDGES + TPB - 1) / TPB, TPB>>>(ei);

    const int gemm_blocks = (N_NODES + 127) / 128;
    const int agg_blocks  = (N_NODES * 32 + TPB - 1) / TPB;

    // 4 GCN layers
    k_gemm<<<gemm_blocks, 256>>>(x,  W[0], gh, N_NODES);
    k_agg<<<agg_blocks, TPB>>>(gh, b[0], ga);
    k_gemm<<<gemm_blocks, 256>>>(ga, W[1], gh, N_NODES);
    k_agg<<<agg_blocks, TPB>>>(gh, b[1], ga);
    k_gemm<<<gemm_blocks, 256>>>(ga, W[2], gh, N_NODES);
    k_agg<<<agg_blocks, TPB>>>(gh, b[2], ga);
    k_gemm<<<gemm_blocks, 256>>>(ga, W[3], gh, N_NODES);
    k_agg<<<agg_blocks, TPB>>>(gh, b[3], ga);

    // pooling
    k_pool_zero<<<(N_GRAPHS * FDIM + TPB - 1) / TPB, TPB>>>(out);
    k_pool<<<agg_blocks, TPB>>>(ga, batch, out);
    k_pool_div<<<(N_GRAPHS * FDIM + TPB - 1) / TPB, TPB>>>(out);
}